// round 6
// baseline (speedup 1.0000x reference)
#include <cuda_runtime.h>
#include <cuda_fp16.h>
#include <math.h>
#include <stdint.h>

#define NMOL 512
#define MA   64
#define FD   128
#define NF   16
#define DIN  (FD * (1 + NF))   // 2176
#define HID  512
#define MTOT (NMOL * MA)       // 32768

// Scratch (allocation-free rule: __device__ globals)
__device__ __align__(256) __half g_v[(size_t)MTOT * DIN];    // 142 MB
__device__ __align__(256) __half g_w1t[(size_t)HID * DIN];   // [N][K]
__device__ __align__(256) __half g_w2t[(size_t)FD * HID];    // [N][K]
__device__ __align__(256) __half g_t[(size_t)MTOT * HID];    // 33 MB

// ===================== low-level helpers ===================================
__device__ __forceinline__ uint32_t smem_u32(const void* p) {
    uint32_t a;
    asm("{ .reg .u64 t; cvta.to.shared.u64 t, %1; cvt.u32.u64 %0, t; }"
        : "=r"(a) : "l"(p));
    return a;
}
#define CP_ASYNC16(s, g) \
    asm volatile("cp.async.cg.shared.global [%0], [%1], 16;" :: "r"(s), "l"(g))
#define CP_COMMIT() asm volatile("cp.async.commit_group;")
#define CP_WAIT1()  asm volatile("cp.async.wait_group 1;" ::: "memory")
#define CP_WAIT2()  asm volatile("cp.async.wait_group 2;" ::: "memory")

__device__ __forceinline__ void ldsm_x4(uint32_t& r0, uint32_t& r1,
                                        uint32_t& r2, uint32_t& r3, uint32_t a) {
    asm volatile("ldmatrix.sync.aligned.m8n8.x4.shared.b16 {%0,%1,%2,%3}, [%4];"
                 : "=r"(r0), "=r"(r1), "=r"(r2), "=r"(r3) : "r"(a));
}
__device__ __forceinline__ void ldsm_x4_t(uint32_t& r0, uint32_t& r1,
                                          uint32_t& r2, uint32_t& r3, uint32_t a) {
    asm volatile("ldmatrix.sync.aligned.m8n8.x4.trans.shared.b16 {%0,%1,%2,%3}, [%4];"
                 : "=r"(r0), "=r"(r1), "=r"(r2), "=r"(r3) : "r"(a));
}
__device__ __forceinline__ void mma16816(float d[4],
    uint32_t a0, uint32_t a1, uint32_t a2, uint32_t a3, uint32_t b0, uint32_t b1) {
    asm volatile(
        "mma.sync.aligned.m16n8k16.row.col.f32.f16.f16.f32 "
        "{%0,%1,%2,%3}, {%4,%5,%6,%7}, {%8,%9}, {%0,%1,%2,%3};"
        : "+f"(d[0]), "+f"(d[1]), "+f"(d[2]), "+f"(d[3])
        : "r"(a0), "r"(a1), "r"(a2), "r"(a3), "r"(b0), "r"(b1));
}
// 64B-row tile swizzle: 4x 16B chunks per row, phys chunk = c ^ ((row>>1)&3)
__device__ __forceinline__ uint32_t swz64(uint32_t base, int row, int chunk) {
    return base + row * 64 + (((chunk ^ (row >> 1)) & 3) << 4);
}

// ===================== weight prep (f32 -> transposed fp16) ================
__global__ void prep_w1_kernel(const float* __restrict__ W1) {
    __shared__ float tile[32][33];
    int n0 = blockIdx.x * 32, k0 = blockIdx.y * 32;
    int tx = threadIdx.x, ty = threadIdx.y;
    for (int rr = ty; rr < 32; rr += 8)
        tile[rr][tx] = W1[(size_t)(k0 + rr) * HID + n0 + tx];
    __syncthreads();
    for (int rr = ty; rr < 32; rr += 8)
        g_w1t[(size_t)(n0 + rr) * DIN + k0 + tx] = __float2half(tile[tx][rr]);
}
__global__ void prep_w2_kernel(const float* __restrict__ W2) {
    __shared__ float tile[32][33];
    int n0 = blockIdx.x * 32, k0 = blockIdx.y * 32;
    int tx = threadIdx.x, ty = threadIdx.y;
    for (int rr = ty; rr < 32; rr += 8)
        tile[rr][tx] = W2[(size_t)(k0 + rr) * FD + n0 + tx];
    __syncthreads();
    for (int rr = ty; rr < 32; rr += 8)
        g_w2t[(size_t)(n0 + rr) * HID + k0 + tx] = __float2half(tile[tx][rr]);
}

// ===========================================================================
// Kernel A: per-molecule RBF message passing -> v (fp16) = concat(h, u)
// Batched-f: stack 4 RBF channels into M=256 rows, one 256x128x64 MMA pass,
// 4 passes total (2 barriers each, vs 32 barriers before).
// dyn smem: shh 16KB (h) + swh 32KB (4-channel w stack) + sd 16KB = 64KB.
// ===========================================================================
__global__ __launch_bounds__(256) void build_v_kernel(
    const int* __restrict__ z, const float* __restrict__ r,
    const float* __restrict__ h, const float* __restrict__ distances,
    const float* __restrict__ widths)
{
    __shared__ float sr[MA][3];
    __shared__ float smk[MA];
    __shared__ float s_mu[NF], s_isig[NF];
    extern __shared__ char dynv[];
    char*  shh_c = dynv;                        // 64 x 128 half, 256B rows
    char*  swh_c = dynv + 16384;                // 256 x 64 half, 128B rows
    float* sd    = (float*)(dynv + 16384 + 32768);
    const uint32_t shh_b = smem_u32(shh_c);
    const uint32_t swh_b = smem_u32(swh_c);

    const int n   = blockIdx.x;
    const int tid = threadIdx.x;

    if (tid < MA) {
        size_t base = ((size_t)n * MA + tid);
        sr[tid][0] = r[base * 3 + 0];
        sr[tid][1] = r[base * 3 + 1];
        sr[tid][2] = r[base * 3 + 2];
        smk[tid]   = (z[base] > -1) ? 1.0f : 0.0f;
    }
    if (tid < NF) {
        s_mu[tid]   = distances[tid];
        s_isig[tid] = 1.0f / widths[tid];
    }

    // h -> shh (fp16, swizzled) and v[:, 0:FD] (fp16)
    const float* hb = h + (size_t)n * MA * FD;
    const size_t vrow = (size_t)n * MA;
    for (int V = tid; V < 1024; V += 256) {
        int b = V >> 4, ch = V & 15;
        const float* src = hb + b * FD + ch * 8;
        __half hh[8];
        #pragma unroll
        for (int i = 0; i < 8; i++) hh[i] = __float2half(src[i]);
        *(uint4*)(shh_c + b * 256 + ((ch ^ (b & 7)) << 4)) = *(uint4*)hh;
        *(uint4*)&g_v[(vrow + b) * DIN + ch * 8] = *(uint4*)hh;
    }
    __syncthreads();

    // pairwise distances (fp32)
    for (int i = tid; i < MA * MA; i += 256) {
        int a = i >> 6, b = i & 63;
        float dx = sr[a][0] - sr[b][0];
        float dy = sr[a][1] - sr[b][1];
        float dz = sr[a][2] - sr[b][2];
        sd[i] = sqrtf(fmaf(dx, dx, fmaf(dy, dy, fmaf(dz, dz, 1e-12f))));
    }
    __syncthreads();

    const int lane = tid & 31, w = tid >> 5;
    const int g = lane >> 2, q = lane & 3;
    const int t = lane >> 3, rin = lane & 7;

    for (int p = 0; p < 4; p++) {
        // Fill 4-channel w stack: rows = fi*64 + a, cols = b (fp16, swizzled)
        for (int idx = tid; idx < 8192; idx += 256) {
            int b2 = idx & 31;            // b = 2*b2
            int a  = (idx >> 5) & 63;
            int fi = idx >> 11;
            int f  = p * 4 + fi;
            int row = fi * 64 + a;
            int b = b2 * 2;
            float mu = s_mu[f], isig = s_isig[f];
            float d0 = sd[a * 64 + b]     - mu;
            float d1 = sd[a * 64 + b + 1] - mu;
            float mk = smk[a] * 5.0f;
            float w0 = mk * smk[b]     * __expf(-d0 * d0 * isig);
            float w1 = mk * smk[b + 1] * __expf(-d1 * d1 * isig);
            int chunk = b >> 3;
            *(__half2*)(swh_c + row * 128 + ((chunk ^ (row & 7)) << 4) + (b & 7) * 2)
                = __floats2half2_rn(w0, w1);
        }
        __syncthreads();

        // MMA: stacked 256(m) x 128(n) x 64(k); warp w -> rows [w*32, w*32+32)
        float dacc[2][16][4];
        #pragma unroll
        for (int am = 0; am < 2; am++)
            #pragma unroll
            for (int na = 0; na < 16; na++)
                #pragma unroll
                for (int i = 0; i < 4; i++) dacc[am][na][i] = 0.0f;

        #pragma unroll
        for (int ks = 0; ks < 4; ks++) {
            uint32_t af[2][4];
            #pragma unroll
            for (int am = 0; am < 2; am++) {
                int arow = w * 32 + am * 16 + (t & 1) * 8 + rin;
                int ach  = ks * 2 + (t >> 1);
                ldsm_x4(af[am][0], af[am][1], af[am][2], af[am][3],
                        swh_b + arow * 128 + (((ach ^ (arow & 7)) & 7) << 4));
            }
            #pragma unroll
            for (int np = 0; np < 8; np++) {
                uint32_t r0, r1, r2, r3;
                int brow = ks * 16 + (t & 1) * 8 + rin;
                int bch  = np * 2 + (t >> 1);
                ldsm_x4_t(r0, r1, r2, r3,
                          shh_b + brow * 256 + (((bch ^ (brow & 7)) & 15) << 4));
                mma16816(dacc[0][np * 2],     af[0][0], af[0][1], af[0][2], af[0][3], r0, r1);
                mma16816(dacc[0][np * 2 + 1], af[0][0], af[0][1], af[0][2], af[0][3], r2, r3);
                mma16816(dacc[1][np * 2],     af[1][0], af[1][1], af[1][2], af[1][3], r0, r1);
                mma16816(dacc[1][np * 2 + 1], af[1][0], af[1][1], af[1][2], af[1][3], r2, r3);
            }
        }

        // store u -> v[:, FD + f*128 + c]; warp covers one fi = w>>1
        {
            int f     = p * 4 + (w >> 1);
            int abase = (w & 1) * 32;
            #pragma unroll
            for (int am = 0; am < 2; am++) {
                int a = abase + am * 16 + g;
                #pragma unroll
                for (int na = 0; na < 16; na++) {
                    int col = FD + f * FD + na * 8 + q * 2;
                    __half2 lo = __floats2half2_rn(dacc[am][na][0], dacc[am][na][1]);
                    __half2 hi = __floats2half2_rn(dacc[am][na][2], dacc[am][na][3]);
                    *(__half2*)&g_v[(vrow + a) * DIN + col]     = lo;
                    *(__half2*)&g_v[(vrow + a + 8) * DIN + col] = hi;
                }
            }
        }
        __syncthreads();
    }
}

// ===========================================================================
// gemm1 core: CTA 128(M) x 256(N), BK=32, 4-stage cp.async, 8 warps (2m x 4n),
// warp tile 64x64, m16n8k16 f32-accum.
// smem: 4 x (8KB A + 16KB B) = 96KB.
// ===========================================================================
#define G1_ASLOT 8192
#define G1_BSLOT 16384

__device__ __forceinline__ void g1_load_stage(uint32_t sA, uint32_t sB,
    const __half* __restrict__ A, const __half* __restrict__ B, int kc, int tid)
{
    #pragma unroll
    for (int i = 0; i < 2; i++) {
        int V = tid + i * 256;
        int m = V >> 2, c = V & 3;
        CP_ASYNC16(swz64(sA, m, c), A + (size_t)m * DIN + kc + c * 8);
    }
    #pragma unroll
    for (int i = 0; i < 4; i++) {
        int V = tid + i * 256;
        int nn = V >> 2, c = V & 3;
        CP_ASYNC16(swz64(sB, nn, c), B + (size_t)nn * DIN + kc + c * 8);
    }
}

__device__ __forceinline__ void g1_compute(uint32_t sA, uint32_t sB, int tid,
                                           float d[4][8][4])
{
    const int lane = tid & 31, w = tid >> 5;
    const int wm = (w & 1) * 64, wn = (w >> 1) * 64;
    const int t = lane >> 3, rin = lane & 7;

    uint32_t bf[8][4];
    {
        int brow = wn + (lane & 7);
        int bch  = lane >> 3;
        #pragma unroll
        for (int na = 0; na < 8; na++)
            ldsm_x4(bf[na][0], bf[na][1], bf[na][2], bf[na][3],
                    swz64(sB, brow + na * 8, bch));
    }
    #pragma unroll
    for (int ks = 0; ks < 2; ks++) {
        uint32_t af[4][4];
        int arow = wm + (t & 1) * 8 + rin;
        int ach  = ks * 2 + (t >> 1);
        #pragma unroll
        for (int ma = 0; ma < 4; ma++)
            ldsm_x4(af[ma][0], af[ma][1], af[ma][2], af[ma][3],
                    swz64(sA, arow + ma * 16, ach));
        #pragma unroll
        for (int ma = 0; ma < 4; ma++)
            #pragma unroll
            for (int na = 0; na < 8; na++)
                mma16816(d[ma][na], af[ma][0], af[ma][1], af[ma][2], af[ma][3],
                         bf[na][ks * 2], bf[na][ks * 2 + 1]);
    }
}

__global__ __launch_bounds__(256, 1) void gemm1_kernel(const float* __restrict__ b1)
{
    extern __shared__ __align__(128) char smem[];
    uint32_t sA0 = smem_u32(smem), sB0 = sA0 + 4 * G1_ASLOT;
    const int tid = threadIdx.x;
    const int bx = blockIdx.x, by = blockIdx.y;
    const int nchunks = DIN / 32;   // 68

    const __half* A = g_v   + (size_t)by * 128 * DIN;
    const __half* B = g_w1t + (size_t)bx * 256 * DIN;

    float d[4][8][4];
    #pragma unroll
    for (int ma = 0; ma < 4; ma++)
        #pragma unroll
        for (int na = 0; na < 8; na++)
            #pragma unroll
            for (int i = 0; i < 4; i++) d[ma][na][i] = 0.0f;

    #pragma unroll
    for (int st = 0; st < 3; st++) {
        g1_load_stage(sA0 + st * G1_ASLOT, sB0 + st * G1_BSLOT, A, B, st * 32, tid);
        CP_COMMIT();
    }
    for (int c = 0; c < nchunks; c++) {
        CP_WAIT2();
        __syncthreads();
        int nc = c + 3;
        if (nc < nchunks)
            g1_load_stage(sA0 + (nc & 3) * G1_ASLOT, sB0 + (nc & 3) * G1_BSLOT,
                          A, B, nc * 32, tid);
        CP_COMMIT();
        g1_compute(sA0 + (c & 3) * G1_ASLOT, sB0 + (c & 3) * G1_BSLOT, tid, d);
    }

    // Epilogue: bias + SiLU -> g_t fp16
    const int lane = tid & 31, w = tid >> 5;
    const int g2 = lane >> 2, q = lane & 3;
    const int wm = (w & 1) * 64, wn = (w >> 1) * 64;
    #pragma unroll
    for (int ma = 0; ma < 4; ma++) {
        int r0 = by * 128 + wm + ma * 16 + g2;
        #pragma unroll
        for (int na = 0; na < 8; na++) {
            int cn = bx * 256 + wn + na * 8 + q * 2;
            float bb0 = b1[cn], bb1 = b1[cn + 1];
            float x0 = d[ma][na][0] + bb0;
            float x1 = d[ma][na][1] + bb1;
            float x2 = d[ma][na][2] + bb0;
            float x3 = d[ma][na][3] + bb1;
            x0 = x0 / (1.0f + __expf(-x0));
            x1 = x1 / (1.0f + __expf(-x1));
            x2 = x2 / (1.0f + __expf(-x2));
            x3 = x3 / (1.0f + __expf(-x3));
            *(__half2*)&g_t[(size_t)r0 * HID + cn]       = __floats2half2_rn(x0, x1);
            *(__half2*)&g_t[(size_t)(r0 + 8) * HID + cn] = __floats2half2_rn(x2, x3);
        }
    }
}

// ===========================================================================
// gemm2 core (proven round-5 path): CTA 128x128, BK=32, 3-stage, warp 64x32.
// ===========================================================================
__device__ __forceinline__ void g2_load_stage(uint32_t sA, uint32_t sB,
    const __half* __restrict__ A, int lda, const __half* __restrict__ B, int ldb,
    int kc, int tid)
{
    #pragma unroll
    for (int i = 0; i < 2; i++) {
        int V = tid + i * 256;
        int m = V >> 2, c = V & 3;
        CP_ASYNC16(swz64(sA, m, c), A + (size_t)m * lda + kc + c * 8);
        CP_ASYNC16(swz64(sB, m, c), B + (size_t)m * ldb + kc + c * 8);
    }
}

__device__ __forceinline__ void g2_compute(uint32_t sA, uint32_t sB, int tid,
                                           float d[4][4][4])
{
    const int lane = tid & 31, w = tid >> 5;
    const int wm = (w & 1) * 64, wn = (w >> 1) * 32;
    const int t = lane >> 3, rin = lane & 7;

    uint32_t bf[4][4];
    {
        int brow = wn + (lane & 7);
        int bch  = lane >> 3;
        #pragma unroll
        for (int na = 0; na < 4; na++)
            ldsm_x4(bf[na][0], bf[na][1], bf[na][2], bf[na][3],
                    swz64(sB, brow + na * 8, bch));
    }
    #pragma unroll
    for (int ks = 0; ks < 2; ks++) {
        uint32_t af[4][4];
        int arow = wm + (t & 1) * 8 + rin;
        int ach  = ks * 2 + (t >> 1);
        #pragma unroll
        for (int ma = 0; ma < 4; ma++)
            ldsm_x4(af[ma][0], af[ma][1], af[ma][2], af[ma][3],
                    swz64(sA, arow + ma * 16, ach));
        #pragma unroll
        for (int ma = 0; ma < 4; ma++)
            #pragma unroll
            for (int na = 0; na < 4; na++)
                mma16816(d[ma][na], af[ma][0], af[ma][1], af[ma][2], af[ma][3],
                         bf[na][ks * 2], bf[na][ks * 2 + 1]);
    }
}

__global__ __launch_bounds__(256) void gemm2_kernel(
    const float* __restrict__ b2, const float* __restrict__ h,
    const int* __restrict__ z, float* __restrict__ out_h)
{
    extern __shared__ __align__(128) char smem[];
    uint32_t sA0 = smem_u32(smem), sB0 = sA0 + 3 * 8192;
    const int tid = threadIdx.x;
    const int by = blockIdx.x;
    const int nchunks = HID / 32;

    const __half* A = g_t + (size_t)by * 128 * HID;
    const __half* B = g_w2t;

    float d[4][4][4];
    #pragma unroll
    for (int ma = 0; ma < 4; ma++)
        #pragma unroll
        for (int na = 0; na < 4; na++)
            #pragma unroll
            for (int i = 0; i < 4; i++) d[ma][na][i] = 0.0f;

    g2_load_stage(sA0,        sB0,        A, HID, B, HID, 0,  tid); CP_COMMIT();
    g2_load_stage(sA0 + 8192, sB0 + 8192, A, HID, B, HID, 32, tid); CP_COMMIT();
    for (int c = 0; c < nchunks; c++) {
        CP_WAIT1();
        __syncthreads();
        int nc = c + 2;
        if (nc < nchunks) {
            int slot = nc - (nc / 3) * 3;
            g2_load_stage(sA0 + slot * 8192, sB0 + slot * 8192,
                          A, HID, B, HID, nc * 32, tid);
        }
        CP_COMMIT();
        int cs = c - (c / 3) * 3;
        g2_compute(sA0 + cs * 8192, sB0 + cs * 8192, tid, d);
    }

    const int lane = tid & 31, w = tid >> 5;
    const int g2r = lane >> 2, q = lane & 3;
    const int wm = (w & 1) * 64, wn = (w >> 1) * 32;
    #pragma unroll
    for (int ma = 0; ma < 4; ma++) {
        int r0 = by * 128 + wm + ma * 16 + g2r;
        int r8 = r0 + 8;
        float m0 = (z[r0] > -1) ? 0.1f : 0.0f;
        float m8 = (z[r8] > -1) ? 0.1f : 0.0f;
        #pragma unroll
        for (int na = 0; na < 4; na++) {
            int cn = wn + na * 8 + q * 2;
            float bb0 = b2[cn], bb1 = b2[cn + 1];
            float2 h0 = *(const float2*)&h[(size_t)r0 * FD + cn];
            float2 h8 = *(const float2*)&h[(size_t)r8 * FD + cn];
            float2 o0, o8;
            o0.x = h0.x + (d[ma][na][0] + bb0) * m0;
            o0.y = h0.y + (d[ma][na][1] + bb1) * m0;
            o8.x = h8.x + (d[ma][na][2] + bb0) * m8;
            o8.y = h8.y + (d[ma][na][3] + bb1) * m8;
            *(float2*)&out_h[(size_t)r0 * FD + cn] = o0;
            *(float2*)&out_h[(size_t)r8 * FD + cn] = o8;
        }
    }
}

// ---------------------------------------------------------------------------
// Kernel D: pass-through z (as float) and r for the tuple output layout.
// ---------------------------------------------------------------------------
__global__ void copy_zr_kernel(const int* __restrict__ z,
                               const float* __restrict__ r,
                               float* __restrict__ out)
{
    int i = blockIdx.x * 256 + threadIdx.x;
    const int nz = NMOL * MA;
    const int nr = NMOL * MA * 3;
    if (i < nz)            out[i] = (float)z[i];
    else if (i < nz + nr)  out[i] = r[i - nz];
}

extern "C" void kernel_launch(void* const* d_in, const int* in_sizes, int n_in,
                              void* d_out, int out_size)
{
    const int*   z         = (const int*)  d_in[0];
    const float* r         = (const float*)d_in[1];
    const float* h         = (const float*)d_in[2];
    const float* distances = (const float*)d_in[3];
    const float* widths    = (const float*)d_in[4];
    const float* W1        = (const float*)d_in[5];
    const float* b1        = (const float*)d_in[6];
    const float* W2        = (const float*)d_in[7];
    const float* b2        = (const float*)d_in[8];

    float* out   = (float*)d_out;
    float* out_h = out;
    const int nz = NMOL * MA;
    const int nr = NMOL * MA * 3;
    const int nh = NMOL * MA * FD;
    if (out_size >= nz + nr + nh) {
        copy_zr_kernel<<<(nz + nr + 255) / 256, 256>>>(z, r, out);
        out_h = out + nz + nr;
    }

    cudaFuncSetAttribute(build_v_kernel,
                         cudaFuncAttributeMaxDynamicSharedMemorySize, 65536);
    cudaFuncSetAttribute(gemm1_kernel,
                         cudaFuncAttributeMaxDynamicSharedMemorySize, 98304);
    cudaFuncSetAttribute(gemm2_kernel,
                         cudaFuncAttributeMaxDynamicSharedMemorySize, 49152);

    prep_w1_kernel<<<dim3(HID / 32, DIN / 32), dim3(32, 8)>>>(W1);
    prep_w2_kernel<<<dim3(FD / 32, HID / 32), dim3(32, 8)>>>(W2);
    build_v_kernel<<<NMOL, 256, 65536>>>(z, r, h, distances, widths);
    gemm1_kernel<<<dim3(HID / 256, MTOT / 128), 256, 98304>>>(b1);
    gemm2_kernel<<<MTOT / 128, 256, 49152>>>(b2, h, z, out_h);
}

// round 11
// speedup vs baseline: 1.2405x; 1.2405x over previous
#include <cuda_runtime.h>
#include <cuda_fp16.h>
#include <math.h>
#include <stdint.h>

#define NMOL 512
#define MA   64
#define FD   128
#define NF   16
#define DIN  (FD * (1 + NF))   // 2176
#define HID  512
#define MTOT (NMOL * MA)       // 32768

// Scratch (allocation-free rule: __device__ globals)
__device__ __align__(256) __half g_v[(size_t)MTOT * DIN];    // 142 MB
__device__ __align__(256) __half g_w1t[(size_t)HID * DIN];   // [N][K]
__device__ __align__(256) __half g_w2t[(size_t)FD * HID];    // [N][K]
__device__ __align__(256) __half g_t[(size_t)MTOT * HID];    // 33 MB

// ===================== low-level helpers ===================================
__device__ __forceinline__ uint32_t smem_u32(const void* p) {
    uint32_t a;
    asm("{ .reg .u64 t; cvta.to.shared.u64 t, %1; cvt.u32.u64 %0, t; }"
        : "=r"(a) : "l"(p));
    return a;
}
#define CP_ASYNC16(s, g) \
    asm volatile("cp.async.cg.shared.global [%0], [%1], 16;" :: "r"(s), "l"(g))
#define CP_COMMIT() asm volatile("cp.async.commit_group;")
#define CP_WAIT1()  asm volatile("cp.async.wait_group 1;" ::: "memory")
#define CP_WAIT2()  asm volatile("cp.async.wait_group 2;" ::: "memory")

__device__ __forceinline__ void ldsm_x4(uint32_t& r0, uint32_t& r1,
                                        uint32_t& r2, uint32_t& r3, uint32_t a) {
    asm volatile("ldmatrix.sync.aligned.m8n8.x4.shared.b16 {%0,%1,%2,%3}, [%4];"
                 : "=r"(r0), "=r"(r1), "=r"(r2), "=r"(r3) : "r"(a));
}
__device__ __forceinline__ void ldsm_x4_t(uint32_t& r0, uint32_t& r1,
                                          uint32_t& r2, uint32_t& r3, uint32_t a) {
    asm volatile("ldmatrix.sync.aligned.m8n8.x4.trans.shared.b16 {%0,%1,%2,%3}, [%4];"
                 : "=r"(r0), "=r"(r1), "=r"(r2), "=r"(r3) : "r"(a));
}
__device__ __forceinline__ void mma16816(float d[4],
    uint32_t a0, uint32_t a1, uint32_t a2, uint32_t a3, uint32_t b0, uint32_t b1) {
    asm volatile(
        "mma.sync.aligned.m16n8k16.row.col.f32.f16.f16.f32 "
        "{%0,%1,%2,%3}, {%4,%5,%6,%7}, {%8,%9}, {%0,%1,%2,%3};"
        : "+f"(d[0]), "+f"(d[1]), "+f"(d[2]), "+f"(d[3])
        : "r"(a0), "r"(a1), "r"(a2), "r"(a3), "r"(b0), "r"(b1));
}
// 64B-row tile swizzle: 4x 16B chunks per row, phys chunk = c ^ ((row>>1)&3)
__device__ __forceinline__ uint32_t swz64(uint32_t base, int row, int chunk) {
    return base + row * 64 + (((chunk ^ (row >> 1)) & 3) << 4);
}

// ===================== weight prep (f32 -> transposed fp16) ================
__global__ void prep_w1_kernel(const float* __restrict__ W1) {
    __shared__ float tile[32][33];
    int n0 = blockIdx.x * 32, k0 = blockIdx.y * 32;
    int tx = threadIdx.x, ty = threadIdx.y;
    for (int rr = ty; rr < 32; rr += 8)
        tile[rr][tx] = W1[(size_t)(k0 + rr) * HID + n0 + tx];
    __syncthreads();
    for (int rr = ty; rr < 32; rr += 8)
        g_w1t[(size_t)(n0 + rr) * DIN + k0 + tx] = __float2half(tile[tx][rr]);
}
__global__ void prep_w2_kernel(const float* __restrict__ W2) {
    __shared__ float tile[32][33];
    int n0 = blockIdx.x * 32, k0 = blockIdx.y * 32;
    int tx = threadIdx.x, ty = threadIdx.y;
    for (int rr = ty; rr < 32; rr += 8)
        tile[rr][tx] = W2[(size_t)(k0 + rr) * FD + n0 + tx];
    __syncthreads();
    for (int rr = ty; rr < 32; rr += 8)
        g_w2t[(size_t)(n0 + rr) * HID + k0 + tx] = __float2half(tile[tx][rr]);
}

// ===========================================================================
// Kernel A: per-molecule RBF message passing -> v (fp16) = concat(h, u)
// Round-5 structure + double-buffered w: fill w[f+1] overlaps mma on w[f],
// ONE barrier per f (16 total) instead of two (32).
// dyn smem: shh 16KB + w bufs 2x8KB + sd 16KB = 48KB.
// ===========================================================================
__global__ __launch_bounds__(256) void build_v_kernel(
    const int* __restrict__ z, const float* __restrict__ r,
    const float* __restrict__ h, const float* __restrict__ distances,
    const float* __restrict__ widths)
{
    __shared__ float sr[MA][3];
    __shared__ float smk[MA];
    __shared__ float s_mu[NF], s_isig[NF];
    extern __shared__ char dynv[];
    char*  shh_c = dynv;                       // 64 x 128 half, 256B rows
    char*  swh_c = dynv + 16384;               // 2 x (64 x 64 half, 128B rows)
    float* sd    = (float*)(dynv + 16384 + 16384);
    const uint32_t shh_b = smem_u32(shh_c);
    const uint32_t swh_b = smem_u32(swh_c);

    const int n   = blockIdx.x;
    const int tid = threadIdx.x;

    if (tid < MA) {
        size_t base = ((size_t)n * MA + tid);
        sr[tid][0] = r[base * 3 + 0];
        sr[tid][1] = r[base * 3 + 1];
        sr[tid][2] = r[base * 3 + 2];
        smk[tid]   = (z[base] > -1) ? 1.0f : 0.0f;
    }
    if (tid < NF) {
        s_mu[tid]   = distances[tid];
        s_isig[tid] = 1.0f / widths[tid];
    }

    // h -> shh (fp16, swizzled) and v[:, 0:FD] (fp16)
    const float* hb = h + (size_t)n * MA * FD;
    const size_t vrow = (size_t)n * MA;
    for (int V = tid; V < 1024; V += 256) {
        int b = V >> 4, ch = V & 15;
        const float* src = hb + b * FD + ch * 8;
        __half hh[8];
        #pragma unroll
        for (int i = 0; i < 8; i++) hh[i] = __float2half(src[i]);
        *(uint4*)(shh_c + b * 256 + ((ch ^ (b & 7)) << 4)) = *(uint4*)hh;
        *(uint4*)&g_v[(vrow + b) * DIN + ch * 8] = *(uint4*)hh;
    }
    __syncthreads();

    // pairwise distances (fp32)
    for (int i = tid; i < MA * MA; i += 256) {
        int a = i >> 6, b = i & 63;
        float dx = sr[a][0] - sr[b][0];
        float dy = sr[a][1] - sr[b][1];
        float dz = sr[a][2] - sr[b][2];
        sd[i] = sqrtf(fmaf(dx, dx, fmaf(dy, dy, fmaf(dz, dz, 1e-12f))));
    }
    __syncthreads();

    const int lane = tid & 31, w = tid >> 5;
    const int g = lane >> 2, q = lane & 3;
    const int t = lane >> 3, rin = lane & 7;
    const int wa = (w & 3) * 16;        // m-atom row base (0,16,32,48)
    const int nh = (w >> 2) * 64;       // n half (0 or 64)

    // fill w for channel f into buffer (f & 1)
    auto fill_w = [&](int f) {
        char* buf = swh_c + (f & 1) * 8192;
        const float mu = s_mu[f], inv_sig = s_isig[f];
        #pragma unroll 4
        for (int i = tid; i < MA * MA; i += 256) {
            int a = i >> 6, b = i & 63;
            float dd = sd[i] - mu;
            float wv = smk[a] * smk[b] * 5.0f * __expf(-dd * dd * inv_sig);
            *(__half*)(buf + a * 128 + (((b >> 3) ^ (a & 7)) << 4) + (b & 7) * 2)
                = __float2half(wv);
        }
    };

    fill_w(0);
    __syncthreads();

    for (int f = 0; f < NF; f++) {
        if (f + 1 < NF) fill_w(f + 1);   // overlaps with mma below (diff pipes)

        const uint32_t wbuf = swh_b + (f & 1) * 8192;
        float dacc[8][4];
        #pragma unroll
        for (int na = 0; na < 8; na++)
            #pragma unroll
            for (int i = 0; i < 4; i++) dacc[na][i] = 0.0f;

        #pragma unroll
        for (int ks = 0; ks < 4; ks++) {
            uint32_t a0, a1, a2, a3;
            {
                int arow = wa + (t & 1) * 8 + rin;
                int ach  = ks * 2 + (t >> 1);
                ldsm_x4(a0, a1, a2, a3,
                        wbuf + arow * 128 + (((ach ^ (arow & 7)) & 7) << 4));
            }
            #pragma unroll
            for (int np = 0; np < 4; np++) {
                uint32_t r0, r1, r2, r3;
                int brow = ks * 16 + (t & 1) * 8 + rin;
                int bch  = (nh >> 3) + np * 2 + (t >> 1);
                ldsm_x4_t(r0, r1, r2, r3,
                          shh_b + brow * 256 + (((bch ^ (brow & 7)) & 15) << 4));
                mma16816(dacc[np * 2],     a0, a1, a2, a3, r0, r1);
                mma16816(dacc[np * 2 + 1], a0, a1, a2, a3, r2, r3);
            }
        }

        // store u -> v[:, FD + f*128 ...] fp16
        #pragma unroll
        for (int na = 0; na < 8; na++) {
            int ar  = wa + g;
            int col = FD + f * FD + nh + na * 8 + q * 2;
            __half2 lo = __floats2half2_rn(dacc[na][0], dacc[na][1]);
            __half2 hi = __floats2half2_rn(dacc[na][2], dacc[na][3]);
            *(__half2*)&g_v[(vrow + ar) * DIN + col]     = lo;
            *(__half2*)&g_v[(vrow + ar + 8) * DIN + col] = hi;
        }
        __syncthreads();
    }
}

// ===========================================================================
// fp16 GEMM core: CTA 128x128, BK=32, 8 warps (2m x 4n), warp tile 64x32,
// ldmatrix fragments, m16n8k16 f32-accum. (round-5 proven core)
// ===========================================================================
__device__ __forceinline__ void g_load_stage(uint32_t sA, uint32_t sB,
    const __half* __restrict__ A, int lda, const __half* __restrict__ B, int ldb,
    int kc, int tid)
{
    #pragma unroll
    for (int i = 0; i < 2; i++) {
        int V = tid + i * 256;
        int m = V >> 2, c = V & 3;
        CP_ASYNC16(swz64(sA, m, c), A + (size_t)m * lda + kc + c * 8);
        CP_ASYNC16(swz64(sB, m, c), B + (size_t)m * ldb + kc + c * 8);
    }
}

__device__ __forceinline__ void g_compute(uint32_t sA, uint32_t sB, int tid,
                                          float d[4][4][4])
{
    const int lane = tid & 31, w = tid >> 5;
    const int wm = (w & 1) * 64, wn = (w >> 1) * 32;
    const int t = lane >> 3, rin = lane & 7;

    uint32_t bf[4][4];
    {
        int brow = wn + (lane & 7);
        int bch  = lane >> 3;
        #pragma unroll
        for (int na = 0; na < 4; na++)
            ldsm_x4(bf[na][0], bf[na][1], bf[na][2], bf[na][3],
                    swz64(sB, brow + na * 8, bch));
    }
    #pragma unroll
    for (int ks = 0; ks < 2; ks++) {
        uint32_t af[4][4];
        int arow = wm + (t & 1) * 8 + rin;
        int ach  = ks * 2 + (t >> 1);
        #pragma unroll
        for (int ma = 0; ma < 4; ma++)
            ldsm_x4(af[ma][0], af[ma][1], af[ma][2], af[ma][3],
                    swz64(sA, arow + ma * 16, ach));
        #pragma unroll
        for (int ma = 0; ma < 4; ma++)
            #pragma unroll
            for (int na = 0; na < 4; na++)
                mma16816(d[ma][na], af[ma][0], af[ma][1], af[ma][2], af[ma][3],
                         bf[na][ks * 2], bf[na][ks * 2 + 1]);
    }
}

// ---------------------------------------------------------------------------
// Kernel B: t = silu(v @ W1 + b1) -> g_t fp16. M=32768, N=512, K=2176.
// 4-stage cp.async (wait_group 2), smem 4 x (8KB A + 8KB B) = 64KB.
// ---------------------------------------------------------------------------
__global__ __launch_bounds__(256) void gemm1_kernel(const float* __restrict__ b1)
{
    extern __shared__ __align__(128) char smem[];
    uint32_t sA0 = smem_u32(smem), sB0 = sA0 + 4 * 8192;
    const int tid = threadIdx.x;
    const int bx = blockIdx.x, by = blockIdx.y;
    const int nchunks = DIN / 32;   // 68

    const __half* A = g_v   + (size_t)by * 128 * DIN;
    const __half* B = g_w1t + (size_t)bx * 128 * DIN;

    float d[4][4][4];
    #pragma unroll
    for (int ma = 0; ma < 4; ma++)
        #pragma unroll
        for (int na = 0; na < 4; na++)
            #pragma unroll
            for (int i = 0; i < 4; i++) d[ma][na][i] = 0.0f;

    #pragma unroll
    for (int st = 0; st < 3; st++) {
        g_load_stage(sA0 + st * 8192, sB0 + st * 8192, A, DIN, B, DIN, st * 32, tid);
        CP_COMMIT();
    }
    for (int c = 0; c < nchunks; c++) {
        CP_WAIT2();
        __syncthreads();
        int nc = c + 3;
        if (nc < nchunks)
            g_load_stage(sA0 + (nc & 3) * 8192, sB0 + (nc & 3) * 8192,
                         A, DIN, B, DIN, nc * 32, tid);
        CP_COMMIT();
        g_compute(sA0 + (c & 3) * 8192, sB0 + (c & 3) * 8192, tid, d);
    }

    const int lane = tid & 31, w = tid >> 5;
    const int g2 = lane >> 2, q = lane & 3;
    const int wm = (w & 1) * 64, wn = (w >> 1) * 32;
    #pragma unroll
    for (int ma = 0; ma < 4; ma++) {
        int r0 = by * 128 + wm + ma * 16 + g2;
        #pragma unroll
        for (int na = 0; na < 4; na++) {
            int cn = bx * 128 + wn + na * 8 + q * 2;
            float bb0 = b1[cn], bb1 = b1[cn + 1];
            float x0 = d[ma][na][0] + bb0;
            float x1 = d[ma][na][1] + bb1;
            float x2 = d[ma][na][2] + bb0;
            float x3 = d[ma][na][3] + bb1;
            x0 = x0 / (1.0f + __expf(-x0));
            x1 = x1 / (1.0f + __expf(-x1));
            x2 = x2 / (1.0f + __expf(-x2));
            x3 = x3 / (1.0f + __expf(-x3));
            *(__half2*)&g_t[(size_t)r0 * HID + cn]       = __floats2half2_rn(x0, x1);
            *(__half2*)&g_t[(size_t)(r0 + 8) * HID + cn] = __floats2half2_rn(x2, x3);
        }
    }
}

// ---------------------------------------------------------------------------
// Kernel C: h_new = h + (t @ W2 + b2)*0.1*mask. M=32768, N=128, K=512.
// 3-stage (round-5 proven).
// ---------------------------------------------------------------------------
__global__ __launch_bounds__(256) void gemm2_kernel(
    const float* __restrict__ b2, const float* __restrict__ h,
    const int* __restrict__ z, float* __restrict__ out_h)
{
    extern __shared__ __align__(128) char smem[];
    uint32_t sA0 = smem_u32(smem), sB0 = sA0 + 3 * 8192;
    const int tid = threadIdx.x;
    const int by = blockIdx.x;
    const int nchunks = HID / 32;

    const __half* A = g_t + (size_t)by * 128 * HID;
    const __half* B = g_w2t;

    float d[4][4][4];
    #pragma unroll
    for (int ma = 0; ma < 4; ma++)
        #pragma unroll
        for (int na = 0; na < 4; na++)
            #pragma unroll
            for (int i = 0; i < 4; i++) d[ma][na][i] = 0.0f;

    g_load_stage(sA0,        sB0,        A, HID, B, HID, 0,  tid); CP_COMMIT();
    g_load_stage(sA0 + 8192, sB0 + 8192, A, HID, B, HID, 32, tid); CP_COMMIT();
    for (int c = 0; c < nchunks; c++) {
        CP_WAIT1();
        __syncthreads();
        int nc = c + 2;
        if (nc < nchunks) {
            int slot = nc - (nc / 3) * 3;
            g_load_stage(sA0 + slot * 8192, sB0 + slot * 8192,
                         A, HID, B, HID, nc * 32, tid);
        }
        CP_COMMIT();
        int cs = c - (c / 3) * 3;
        g_compute(sA0 + cs * 8192, sB0 + cs * 8192, tid, d);
    }

    const int lane = tid & 31, w = tid >> 5;
    const int g2r = lane >> 2, q = lane & 3;
    const int wm = (w & 1) * 64, wn = (w >> 1) * 32;
    #pragma unroll
    for (int ma = 0; ma < 4; ma++) {
        int r0 = by * 128 + wm + ma * 16 + g2r;
        int r8 = r0 + 8;
        float m0 = (z[r0] > -1) ? 0.1f : 0.0f;
        float m8 = (z[r8] > -1) ? 0.1f : 0.0f;
        #pragma unroll
        for (int na = 0; na < 4; na++) {
            int cn = wn + na * 8 + q * 2;
            float bb0 = b2[cn], bb1 = b2[cn + 1];
            float2 h0 = *(const float2*)&h[(size_t)r0 * FD + cn];
            float2 h8 = *(const float2*)&h[(size_t)r8 * FD + cn];
            float2 o0, o8;
            o0.x = h0.x + (d[ma][na][0] + bb0) * m0;
            o0.y = h0.y + (d[ma][na][1] + bb1) * m0;
            o8.x = h8.x + (d[ma][na][2] + bb0) * m8;
            o8.y = h8.y + (d[ma][na][3] + bb1) * m8;
            *(float2*)&out_h[(size_t)r0 * FD + cn] = o0;
            *(float2*)&out_h[(size_t)r8 * FD + cn] = o8;
        }
    }
}

// ---------------------------------------------------------------------------
// Kernel D: pass-through z (as float) and r for the tuple output layout.
// ---------------------------------------------------------------------------
__global__ void copy_zr_kernel(const int* __restrict__ z,
                               const float* __restrict__ r,
                               float* __restrict__ out)
{
    int i = blockIdx.x * 256 + threadIdx.x;
    const int nz = NMOL * MA;
    const int nr = NMOL * MA * 3;
    if (i < nz)            out[i] = (float)z[i];
    else if (i < nz + nr)  out[i] = r[i - nz];
}

extern "C" void kernel_launch(void* const* d_in, const int* in_sizes, int n_in,
                              void* d_out, int out_size)
{
    const int*   z         = (const int*)  d_in[0];
    const float* r         = (const float*)d_in[1];
    const float* h         = (const float*)d_in[2];
    const float* distances = (const float*)d_in[3];
    const float* widths    = (const float*)d_in[4];
    const float* W1        = (const float*)d_in[5];
    const float* b1        = (const float*)d_in[6];
    const float* W2        = (const float*)d_in[7];
    const float* b2        = (const float*)d_in[8];

    float* out   = (float*)d_out;
    float* out_h = out;
    const int nz = NMOL * MA;
    const int nr = NMOL * MA * 3;
    const int nh = NMOL * MA * FD;
    if (out_size >= nz + nr + nh) {
        copy_zr_kernel<<<(nz + nr + 255) / 256, 256>>>(z, r, out);
        out_h = out + nz + nr;
    }

    cudaFuncSetAttribute(build_v_kernel,
                         cudaFuncAttributeMaxDynamicSharedMemorySize, 49152);
    cudaFuncSetAttribute(gemm1_kernel,
                         cudaFuncAttributeMaxDynamicSharedMemorySize, 65536);
    cudaFuncSetAttribute(gemm2_kernel,
                         cudaFuncAttributeMaxDynamicSharedMemorySize, 49152);

    prep_w1_kernel<<<dim3(HID / 32, DIN / 32), dim3(32, 8)>>>(W1);
    prep_w2_kernel<<<dim3(FD / 32, HID / 32), dim3(32, 8)>>>(W2);
    build_v_kernel<<<NMOL, 256, 49152>>>(z, r, h, distances, widths);
    gemm1_kernel<<<dim3(HID / 128, MTOT / 128), 256, 65536>>>(b1);
    gemm2_kernel<<<MTOT / 128, 256, 49152>>>(b2, h, z, out_h);
}

// round 13
// speedup vs baseline: 1.3126x; 1.0581x over previous
#include <cuda_runtime.h>
#include <cuda_fp16.h>
#include <math.h>
#include <stdint.h>

#define NMOL 512
#define MA   64
#define FD   128
#define NF   16
#define DIN  (FD * (1 + NF))   // 2176
#define HID  512
#define MTOT (NMOL * MA)       // 32768

// Scratch (allocation-free rule: __device__ globals)
__device__ __align__(256) __half g_v[(size_t)MTOT * DIN];    // 142 MB
__device__ __align__(256) __half g_w1t[(size_t)HID * DIN];   // [N][K]
__device__ __align__(256) __half g_w2t[(size_t)FD * HID];    // [N][K]
__device__ __align__(256) __half g_t[(size_t)MTOT * HID];    // 33 MB

// ===================== low-level helpers ===================================
__device__ __forceinline__ uint32_t smem_u32(const void* p) {
    uint32_t a;
    asm("{ .reg .u64 t; cvta.to.shared.u64 t, %1; cvt.u32.u64 %0, t; }"
        : "=r"(a) : "l"(p));
    return a;
}
#define CP_ASYNC16(s, g) \
    asm volatile("cp.async.cg.shared.global [%0], [%1], 16;" :: "r"(s), "l"(g))
#define CP_COMMIT() asm volatile("cp.async.commit_group;")
#define CP_WAIT1()  asm volatile("cp.async.wait_group 1;" ::: "memory")
#define CP_WAIT2()  asm volatile("cp.async.wait_group 2;" ::: "memory")

__device__ __forceinline__ void ldsm_x4(uint32_t& r0, uint32_t& r1,
                                        uint32_t& r2, uint32_t& r3, uint32_t a) {
    asm volatile("ldmatrix.sync.aligned.m8n8.x4.shared.b16 {%0,%1,%2,%3}, [%4];"
                 : "=r"(r0), "=r"(r1), "=r"(r2), "=r"(r3) : "r"(a));
}
__device__ __forceinline__ void ldsm_x4_t(uint32_t& r0, uint32_t& r1,
                                          uint32_t& r2, uint32_t& r3, uint32_t a) {
    asm volatile("ldmatrix.sync.aligned.m8n8.x4.trans.shared.b16 {%0,%1,%2,%3}, [%4];"
                 : "=r"(r0), "=r"(r1), "=r"(r2), "=r"(r3) : "r"(a));
}
__device__ __forceinline__ void mma16816(float d[4],
    uint32_t a0, uint32_t a1, uint32_t a2, uint32_t a3, uint32_t b0, uint32_t b1) {
    asm volatile(
        "mma.sync.aligned.m16n8k16.row.col.f32.f16.f16.f32 "
        "{%0,%1,%2,%3}, {%4,%5,%6,%7}, {%8,%9}, {%0,%1,%2,%3};"
        : "+f"(d[0]), "+f"(d[1]), "+f"(d[2]), "+f"(d[3])
        : "r"(a0), "r"(a1), "r"(a2), "r"(a3), "r"(b0), "r"(b1));
}
// 64B-row tile swizzle: 4x 16B chunks per row, phys chunk = c ^ ((row>>1)&3)
__device__ __forceinline__ uint32_t swz64(uint32_t base, int row, int chunk) {
    return base + row * 64 + (((chunk ^ (row >> 1)) & 3) << 4);
}

// ===================== weight prep (f32 -> transposed fp16) ================
__global__ void prep_w1_kernel(const float* __restrict__ W1) {
    __shared__ float tile[32][33];
    int n0 = blockIdx.x * 32, k0 = blockIdx.y * 32;
    int tx = threadIdx.x, ty = threadIdx.y;
    for (int rr = ty; rr < 32; rr += 8)
        tile[rr][tx] = W1[(size_t)(k0 + rr) * HID + n0 + tx];
    __syncthreads();
    for (int rr = ty; rr < 32; rr += 8)
        g_w1t[(size_t)(n0 + rr) * DIN + k0 + tx] = __float2half(tile[tx][rr]);
}
__global__ void prep_w2_kernel(const float* __restrict__ W2) {
    __shared__ float tile[32][33];
    int n0 = blockIdx.x * 32, k0 = blockIdx.y * 32;
    int tx = threadIdx.x, ty = threadIdx.y;
    for (int rr = ty; rr < 32; rr += 8)
        tile[rr][tx] = W2[(size_t)(k0 + rr) * FD + n0 + tx];
    __syncthreads();
    for (int rr = ty; rr < 32; rr += 8)
        g_w2t[(size_t)(n0 + rr) * HID + k0 + tx] = __float2half(tile[tx][rr]);
}

// ===========================================================================
// Kernel A: per-molecule RBF message passing -> v (fp16) = concat(h, u)
// Double-buffered w (fill overlaps mma) + smem-staged u epilogue:
// mma frags -> su (conflict-free STS, 272B pitch) -> coalesced STG.128.
// dyn smem: shh 16K + w 2x8K + sd 16K + su 17K = ~65KB (3 CTAs/SM).
// ===========================================================================
#define SU_PITCH 272

__global__ __launch_bounds__(256) void build_v_kernel(
    const int* __restrict__ z, const float* __restrict__ r,
    const float* __restrict__ h, const float* __restrict__ distances,
    const float* __restrict__ widths)
{
    __shared__ float sr[MA][3];
    __shared__ float smk[MA];
    __shared__ float s_mu[NF], s_isig[NF];
    extern __shared__ char dynv[];
    char*  shh_c = dynv;                         // 64 x 128 half, 256B rows
    char*  swh_c = dynv + 16384;                 // 2 x (64 x 64 half, 128B rows)
    float* sd    = (float*)(dynv + 16384 + 16384);
    char*  su_c  = dynv + 16384 + 16384 + 16384; // 64 rows x 272B
    const uint32_t shh_b = smem_u32(shh_c);
    const uint32_t swh_b = smem_u32(swh_c);

    const int n   = blockIdx.x;
    const int tid = threadIdx.x;

    if (tid < MA) {
        size_t base = ((size_t)n * MA + tid);
        sr[tid][0] = r[base * 3 + 0];
        sr[tid][1] = r[base * 3 + 1];
        sr[tid][2] = r[base * 3 + 2];
        smk[tid]   = (z[base] > -1) ? 1.0f : 0.0f;
    }
    if (tid < NF) {
        s_mu[tid]   = distances[tid];
        s_isig[tid] = 1.0f / widths[tid];
    }

    // h -> shh (fp16, swizzled) and v[:, 0:FD] (fp16)
    const float* hb = h + (size_t)n * MA * FD;
    const size_t vrow = (size_t)n * MA;
    for (int V = tid; V < 1024; V += 256) {
        int b = V >> 4, ch = V & 15;
        const float* src = hb + b * FD + ch * 8;
        __half hh[8];
        #pragma unroll
        for (int i = 0; i < 8; i++) hh[i] = __float2half(src[i]);
        *(uint4*)(shh_c + b * 256 + ((ch ^ (b & 7)) << 4)) = *(uint4*)hh;
        *(uint4*)&g_v[(vrow + b) * DIN + ch * 8] = *(uint4*)hh;
    }
    __syncthreads();

    // pairwise distances (fp32)
    for (int i = tid; i < MA * MA; i += 256) {
        int a = i >> 6, b = i & 63;
        float dx = sr[a][0] - sr[b][0];
        float dy = sr[a][1] - sr[b][1];
        float dz = sr[a][2] - sr[b][2];
        sd[i] = sqrtf(fmaf(dx, dx, fmaf(dy, dy, fmaf(dz, dz, 1e-12f))));
    }
    __syncthreads();

    const int lane = tid & 31, w = tid >> 5;
    const int g = lane >> 2, q = lane & 3;
    const int t = lane >> 3, rin = lane & 7;
    const int wa = (w & 3) * 16;        // m-atom row base (0,16,32,48)
    const int nh = (w >> 2) * 64;       // n half (0 or 64)

    // fill w for channel f into buffer (f & 1)
    auto fill_w = [&](int f) {
        char* buf = swh_c + (f & 1) * 8192;
        const float mu = s_mu[f], inv_sig = s_isig[f];
        #pragma unroll 4
        for (int i = tid; i < MA * MA; i += 256) {
            int a = i >> 6, b = i & 63;
            float dd = sd[i] - mu;
            float wv = smk[a] * smk[b] * 5.0f * __expf(-dd * dd * inv_sig);
            *(__half*)(buf + a * 128 + (((b >> 3) ^ (a & 7)) << 4) + (b & 7) * 2)
                = __float2half(wv);
        }
    };

    fill_w(0);
    __syncthreads();

    for (int f = 0; f < NF; f++) {
        const uint32_t wbuf = swh_b + (f & 1) * 8192;
        float dacc[8][4];
        #pragma unroll
        for (int na = 0; na < 8; na++)
            #pragma unroll
            for (int i = 0; i < 4; i++) dacc[na][i] = 0.0f;

        #pragma unroll
        for (int ks = 0; ks < 4; ks++) {
            uint32_t a0, a1, a2, a3;
            {
                int arow = wa + (t & 1) * 8 + rin;
                int ach  = ks * 2 + (t >> 1);
                ldsm_x4(a0, a1, a2, a3,
                        wbuf + arow * 128 + (((ach ^ (arow & 7)) & 7) << 4));
            }
            #pragma unroll
            for (int np = 0; np < 4; np++) {
                uint32_t r0, r1, r2, r3;
                int brow = ks * 16 + (t & 1) * 8 + rin;
                int bch  = (nh >> 3) + np * 2 + (t >> 1);
                ldsm_x4_t(r0, r1, r2, r3,
                          shh_b + brow * 256 + (((bch ^ (brow & 7)) & 15) << 4));
                mma16816(dacc[np * 2],     a0, a1, a2, a3, r0, r1);
                mma16816(dacc[np * 2 + 1], a0, a1, a2, a3, r2, r3);
            }
        }

        // Stage u fragments in smem (conflict-free: word = 68g + q biject banks)
        {
            char* su0 = su_c + (wa + g) * SU_PITCH;
            char* su8 = su0 + 8 * SU_PITCH;
            #pragma unroll
            for (int na = 0; na < 8; na++) {
                int colb = (nh + na * 8 + q * 2) * 2;
                *(__half2*)(su0 + colb) = __floats2half2_rn(dacc[na][0], dacc[na][1]);
                *(__half2*)(su8 + colb) = __floats2half2_rn(dacc[na][2], dacc[na][3]);
            }
        }
        if (f + 1 < NF) fill_w(f + 1);   // overlaps (MUFU/ALU vs LSU)
        __syncthreads();

        // Coalesced flush: 64 rows x 256B, STG.128
        {
            __half* dst = g_v + (vrow)*DIN + FD + f * FD;
            #pragma unroll
            for (int i = 0; i < 4; i++) {
                int V = tid + i * 256;
                int row = V >> 4, c16 = V & 15;
                uint4 val = *(uint4*)(su_c + row * SU_PITCH + c16 * 16);
                *(uint4*)&dst[(size_t)row * DIN + c16 * 8] = val;
            }
        }
        __syncthreads();
    }
}

// ===========================================================================
// fp16 GEMM core: CTA 128x128, BK=32, 8 warps (2m x 4n), warp tile 64x32,
// ldmatrix fragments, m16n8k16 f32-accum. (proven core)
// ===========================================================================
__device__ __forceinline__ void g_load_stage(uint32_t sA, uint32_t sB,
    const __half* __restrict__ A, int lda, const __half* __restrict__ B, int ldb,
    int kc, int tid)
{
    #pragma unroll
    for (int i = 0; i < 2; i++) {
        int V = tid + i * 256;
        int m = V >> 2, c = V & 3;
        CP_ASYNC16(swz64(sA, m, c), A + (size_t)m * lda + kc + c * 8);
        CP_ASYNC16(swz64(sB, m, c), B + (size_t)m * ldb + kc + c * 8);
    }
}

__device__ __forceinline__ void g_compute(uint32_t sA, uint32_t sB, int tid,
                                          float d[4][4][4])
{
    const int lane = tid & 31, w = tid >> 5;
    const int wm = (w & 1) * 64, wn = (w >> 1) * 32;
    const int t = lane >> 3, rin = lane & 7;

    uint32_t bf[4][4];
    {
        int brow = wn + (lane & 7);
        int bch  = lane >> 3;
        #pragma unroll
        for (int na = 0; na < 4; na++)
            ldsm_x4(bf[na][0], bf[na][1], bf[na][2], bf[na][3],
                    swz64(sB, brow + na * 8, bch));
    }
    #pragma unroll
    for (int ks = 0; ks < 2; ks++) {
        uint32_t af[4][4];
        int arow = wm + (t & 1) * 8 + rin;
        int ach  = ks * 2 + (t >> 1);
        #pragma unroll
        for (int ma = 0; ma < 4; ma++)
            ldsm_x4(af[ma][0], af[ma][1], af[ma][2], af[ma][3],
                    swz64(sA, arow + ma * 16, ach));
        #pragma unroll
        for (int ma = 0; ma < 4; ma++)
            #pragma unroll
            for (int na = 0; na < 4; na++)
                mma16816(d[ma][na], af[ma][0], af[ma][1], af[ma][2], af[ma][3],
                         bf[na][ks * 2], bf[na][ks * 2 + 1]);
    }
}

// ---------------------------------------------------------------------------
// Kernel B: t = silu(v @ W1 + b1) -> g_t fp16. M=32768, N=512, K=2176.
// 4-stage cp.async (wait_group 2), smem 4 x (8KB A + 8KB B) = 64KB.
// ---------------------------------------------------------------------------
__global__ __launch_bounds__(256) void gemm1_kernel(const float* __restrict__ b1)
{
    extern __shared__ __align__(128) char smem[];
    uint32_t sA0 = smem_u32(smem), sB0 = sA0 + 4 * 8192;
    const int tid = threadIdx.x;
    const int bx = blockIdx.x, by = blockIdx.y;
    const int nchunks = DIN / 32;   // 68

    const __half* A = g_v   + (size_t)by * 128 * DIN;
    const __half* B = g_w1t + (size_t)bx * 128 * DIN;

    float d[4][4][4];
    #pragma unroll
    for (int ma = 0; ma < 4; ma++)
        #pragma unroll
        for (int na = 0; na < 4; na++)
            #pragma unroll
            for (int i = 0; i < 4; i++) d[ma][na][i] = 0.0f;

    #pragma unroll
    for (int st = 0; st < 3; st++) {
        g_load_stage(sA0 + st * 8192, sB0 + st * 8192, A, DIN, B, DIN, st * 32, tid);
        CP_COMMIT();
    }
    for (int c = 0; c < nchunks; c++) {
        CP_WAIT2();
        __syncthreads();
        int nc = c + 3;
        if (nc < nchunks)
            g_load_stage(sA0 + (nc & 3) * 8192, sB0 + (nc & 3) * 8192,
                         A, DIN, B, DIN, nc * 32, tid);
        CP_COMMIT();
        g_compute(sA0 + (c & 3) * 8192, sB0 + (c & 3) * 8192, tid, d);
    }

    const int lane = tid & 31, w = tid >> 5;
    const int g2 = lane >> 2, q = lane & 3;
    const int wm = (w & 1) * 64, wn = (w >> 1) * 32;
    #pragma unroll
    for (int ma = 0; ma < 4; ma++) {
        int r0 = by * 128 + wm + ma * 16 + g2;
        #pragma unroll
        for (int na = 0; na < 4; na++) {
            int cn = bx * 128 + wn + na * 8 + q * 2;
            float bb0 = b1[cn], bb1 = b1[cn + 1];
            float x0 = d[ma][na][0] + bb0;
            float x1 = d[ma][na][1] + bb1;
            float x2 = d[ma][na][2] + bb0;
            float x3 = d[ma][na][3] + bb1;
            x0 = x0 / (1.0f + __expf(-x0));
            x1 = x1 / (1.0f + __expf(-x1));
            x2 = x2 / (1.0f + __expf(-x2));
            x3 = x3 / (1.0f + __expf(-x3));
            *(__half2*)&g_t[(size_t)r0 * HID + cn]       = __floats2half2_rn(x0, x1);
            *(__half2*)&g_t[(size_t)(r0 + 8) * HID + cn] = __floats2half2_rn(x2, x3);
        }
    }
}

// ---------------------------------------------------------------------------
// Kernel C: h_new = h + (t @ W2 + b2)*0.1*mask. M=32768, N=128, K=512.
// 3-stage (proven).
// ---------------------------------------------------------------------------
__global__ __launch_bounds__(256) void gemm2_kernel(
    const float* __restrict__ b2, const float* __restrict__ h,
    const int* __restrict__ z, float* __restrict__ out_h)
{
    extern __shared__ __align__(128) char smem[];
    uint32_t sA0 = smem_u32(smem), sB0 = sA0 + 3 * 8192;
    const int tid = threadIdx.x;
    const int by = blockIdx.x;
    const int nchunks = HID / 32;

    const __half* A = g_t + (size_t)by * 128 * HID;
    const __half* B = g_w2t;

    float d[4][4][4];
    #pragma unroll
    for (int ma = 0; ma < 4; ma++)
        #pragma unroll
        for (int na = 0; na < 4; na++)
            #pragma unroll
            for (int i = 0; i < 4; i++) d[ma][na][i] = 0.0f;

    g_load_stage(sA0,        sB0,        A, HID, B, HID, 0,  tid); CP_COMMIT();
    g_load_stage(sA0 + 8192, sB0 + 8192, A, HID, B, HID, 32, tid); CP_COMMIT();
    for (int c = 0; c < nchunks; c++) {
        CP_WAIT1();
        __syncthreads();
        int nc = c + 2;
        if (nc < nchunks) {
            int slot = nc - (nc / 3) * 3;
            g_load_stage(sA0 + slot * 8192, sB0 + slot * 8192,
                         A, HID, B, HID, nc * 32, tid);
        }
        CP_COMMIT();
        int cs = c - (c / 3) * 3;
        g_compute(sA0 + cs * 8192, sB0 + cs * 8192, tid, d);
    }

    const int lane = tid & 31, w = tid >> 5;
    const int g2r = lane >> 2, q = lane & 3;
    const int wm = (w & 1) * 64, wn = (w >> 1) * 32;
    #pragma unroll
    for (int ma = 0; ma < 4; ma++) {
        int r0 = by * 128 + wm + ma * 16 + g2r;
        int r8 = r0 + 8;
        float m0 = (z[r0] > -1) ? 0.1f : 0.0f;
        float m8 = (z[r8] > -1) ? 0.1f : 0.0f;
        #pragma unroll
        for (int na = 0; na < 4; na++) {
            int cn = wn + na * 8 + q * 2;
            float bb0 = b2[cn], bb1 = b2[cn + 1];
            float2 h0 = *(const float2*)&h[(size_t)r0 * FD + cn];
            float2 h8 = *(const float2*)&h[(size_t)r8 * FD + cn];
            float2 o0, o8;
            o0.x = h0.x + (d[ma][na][0] + bb0) * m0;
            o0.y = h0.y + (d[ma][na][1] + bb1) * m0;
            o8.x = h8.x + (d[ma][na][2] + bb0) * m8;
            o8.y = h8.y + (d[ma][na][3] + bb1) * m8;
            *(float2*)&out_h[(size_t)r0 * FD + cn] = o0;
            *(float2*)&out_h[(size_t)r8 * FD + cn] = o8;
        }
    }
}

// ---------------------------------------------------------------------------
// Kernel D: pass-through z (as float) and r for the tuple output layout.
// ---------------------------------------------------------------------------
__global__ void copy_zr_kernel(const int* __restrict__ z,
                               const float* __restrict__ r,
                               float* __restrict__ out)
{
    int i = blockIdx.x * 256 + threadIdx.x;
    const int nz = NMOL * MA;
    const int nr = NMOL * MA * 3;
    if (i < nz)            out[i] = (float)z[i];
    else if (i < nz + nr)  out[i] = r[i - nz];
}

extern "C" void kernel_launch(void* const* d_in, const int* in_sizes, int n_in,
                              void* d_out, int out_size)
{
    const int*   z         = (const int*)  d_in[0];
    const float* r         = (const float*)d_in[1];
    const float* h         = (const float*)d_in[2];
    const float* distances = (const float*)d_in[3];
    const float* widths    = (const float*)d_in[4];
    const float* W1        = (const float*)d_in[5];
    const float* b1        = (const float*)d_in[6];
    const float* W2        = (const float*)d_in[7];
    const float* b2        = (const float*)d_in[8];

    float* out   = (float*)d_out;
    float* out_h = out;
    const int nz = NMOL * MA;
    const int nr = NMOL * MA * 3;
    const int nh = NMOL * MA * FD;
    if (out_size >= nz + nr + nh) {
        copy_zr_kernel<<<(nz + nr + 255) / 256, 256>>>(z, r, out);
        out_h = out + nz + nr;
    }

    const int bv_smem = 16384 * 3 + 64 * SU_PITCH;   // ~66.6KB
    cudaFuncSetAttribute(build_v_kernel,
                         cudaFuncAttributeMaxDynamicSharedMemorySize, bv_smem);
    cudaFuncSetAttribute(gemm1_kernel,
                         cudaFuncAttributeMaxDynamicSharedMemorySize, 65536);
    cudaFuncSetAttribute(gemm2_kernel,
                         cudaFuncAttributeMaxDynamicSharedMemorySize, 49152);

    prep_w1_kernel<<<dim3(HID / 32, DIN / 32), dim3(32, 8)>>>(W1);
    prep_w2_kernel<<<dim3(FD / 32, HID / 32), dim3(32, 8)>>>(W2);
    build_v_kernel<<<NMOL, 256, bv_smem>>>(z, r, h, distances, widths);
    gemm1_kernel<<<dim3(HID / 128, MTOT / 128), 256, 65536>>>(b1);
    gemm2_kernel<<<MTOT / 128, 256, 49152>>>(b2, h, z, out_h);
}